// round 14
// baseline (speedup 1.0000x reference)
#include <cuda_runtime.h>
#include <cuda_fp16.h>
#include <cstddef>

// GATNE-T fused (R14): R13 body + PDL (programmatic dependent launch) to
// overlap the fp16 weight-conversion kernel with the main kernel's gather
// phase. cudaGridDependencySynchronize() sits after the gathers, before the
// first read of the converted tables.
//
// Inputs (metadata order):
//  0 targets   int32  [B]
//  1 types     int32  [B]
//  2 neighbors int32  [B,T,S]
//  3 base_node_embeddings float [V,E]
//  4 node_type_embeddings float [V,T,D]
//  5 trans_weights    float [T,D,E]
//  6 trans_weights_s1 float [T,D,A]
//  7 trans_weights_s2 float [T,A,1]
// Output: float [B,E]

namespace {
constexpr int T = 4;
constexpr int S = 10;
constexpr int D = 32;
constexpr int E = 128;
constexpr int A = 32;
constexpr int NW = 8;          // warps per CTA
}

// fp16 weight copies (rebuilt every launch; deterministic).
__device__ __half  g_twh[T * D * E];            // [t][d][e]  (32KB)
__device__ __half2 g_tw1h2[T * (D / 2) * A];    // [t][dp][a]

__device__ __forceinline__ float tanh_approx(float x) {
    float y;
    asm("tanh.approx.f32 %0, %1;" : "=f"(y) : "f"(x));
    return y;
}

// ---------------------------------------------------------------------------
// K0: build fp16 weight tables (tiny).
// ---------------------------------------------------------------------------
__global__ void k_convert(const float* __restrict__ tw,
                          const float* __restrict__ tw1)
{
    const int i = blockIdx.x * blockDim.x + threadIdx.x;
    if (i < T * D * E) g_twh[i] = __float2half_rn(tw[i]);
    if (i < T * (D / 2) * A) {
        const int t  = i / ((D / 2) * A);
        const int r  = i % ((D / 2) * A);
        const int dp = r / A;
        const int a  = r % A;
        const float* p = tw1 + (size_t)t * (D * A);
        g_tw1h2[i] = __floats2half2_rn(p[(2 * dp) * A + a],
                                       p[(2 * dp + 1) * A + a]);
    }
}

// ---------------------------------------------------------------------------
// Main fused kernel: warp-per-b (R13 body + grid-dependency sync).
// ---------------------------------------------------------------------------
__global__ __launch_bounds__(32 * NW, 5) void gatne_warp(
    const int*   __restrict__ targets,
    const int*   __restrict__ types,
    const int*   __restrict__ neighbors,  // [B,T,S]
    const float* __restrict__ base_emb,   // [V,E]
    const float* __restrict__ nte,        // [V,T,D]
    const float* __restrict__ tw2,        // [T,A]
    float*       __restrict__ out,        // [B,E]
    int B)
{
    const int wid  = threadIdx.x >> 5;
    const int lane = threadIdx.x & 31;

    __shared__ float sh_agg[NW][T][D];
    __shared__ float sh_nat[NW][D];

    const int b = blockIdx.x * NW + wid;
    if (b >= B) {
        // still must pass the grid dependency point before exiting
        cudaGridDependencySynchronize();
        return;
    }

    const int ty  = types[b];      // broadcast LDG
    const int tgt = targets[b];    // broadcast LDG

    // PREFETCH the random base_emb gather (overlaps neighbor gathers AND
    // the still-running convert kernel, thanks to PDL).
    const float4 bv = __ldg((const float4*)(base_emb + (size_t)tgt * E) + lane);

    // neighbor indices: 2 coalesced loads for 40 ints
    const int* nbp = neighbors + (size_t)b * (T * S);
    const int nbv0 = nbp[lane];
    const int nbv1 = (lane < T * S - 32) ? nbp[32 + lane] : 0;

    // ---- gather + mean: two explicit 20-wide load batches (pinned MLP) ----
    float acc[T];
    {
        float r0[2 * S];
        #pragma unroll
        for (int s = 0; s < S; ++s) {     // t = 0,1 : 20 loads in flight
            const int v0 = __shfl_sync(0xffffffffu, nbv0, s);
            const int v1 = __shfl_sync(0xffffffffu, nbv0, S + s);
            r0[s]     = __ldg(&nte[(size_t)v0 * (T * D) + 0 * D + lane]);
            r0[S + s] = __ldg(&nte[(size_t)v1 * (T * D) + 1 * D + lane]);
        }
        float a0 = 0.f, a1 = 0.f;
        #pragma unroll
        for (int s = 0; s < S; ++s) { a0 += r0[s]; a1 += r0[S + s]; }

        float r1[2 * S];
        #pragma unroll
        for (int s = 0; s < S; ++s) {     // t = 2,3 : next 20 loads
            const int flat2 = 2 * S + s;
            const int flat3 = 3 * S + s;
            const int v2 = __shfl_sync(0xffffffffu, nbv0, flat2);
            const int v3 = (flat3 < 32)
                ? __shfl_sync(0xffffffffu, nbv0, flat3)
                : __shfl_sync(0xffffffffu, nbv1, flat3 - 32);
            r1[s]     = __ldg(&nte[(size_t)v2 * (T * D) + 2 * D + lane]);
            r1[S + s] = __ldg(&nte[(size_t)v3 * (T * D) + 3 * D + lane]);
        }
        float a2 = 0.f, a3 = 0.f;
        #pragma unroll
        for (int s = 0; s < S; ++s) { a2 += r1[s]; a3 += r1[S + s]; }

        acc[0] = a0 * (1.0f / (float)S);
        acc[1] = a1 * (1.0f / (float)S);
        acc[2] = a2 * (1.0f / (float)S);
        acc[3] = a3 * (1.0f / (float)S);
    }

    #pragma unroll
    for (int t = 0; t < T; ++t) sh_agg[wid][t][lane] = acc[t];
    __syncwarp();

    // ---- PDL: wait for k_convert's writes to be visible before touching
    //      the fp16 tables. Everything above ran concurrently with it. ----
    cudaGridDependencySynchronize();

    // ---- scores: fused 4-t loop, W1 loaded inline as half2 ----
    float s0 = 0.f, s1 = 0.f, s2 = 0.f, s3 = 0.f;
    float z0 = 0.f, z1 = 0.f, z2 = 0.f, z3 = 0.f;
    {
        const __half2* w1h = g_tw1h2 + (size_t)ty * ((D / 2) * A) + lane;
        const float4* ap0 = (const float4*)sh_agg[wid][0];
        const float4* ap1 = (const float4*)sh_agg[wid][1];
        const float4* ap2 = (const float4*)sh_agg[wid][2];
        const float4* ap3 = (const float4*)sh_agg[wid][3];
        #pragma unroll
        for (int q = 0; q < D / 4; ++q) {
            const float2 fa = __half22float2(w1h[(2 * q) * A]);
            const float2 fb = __half22float2(w1h[(2 * q + 1) * A]);
            const float4 v0 = ap0[q];
            const float4 v1 = ap1[q];
            const float4 v2 = ap2[q];
            const float4 v3 = ap3[q];
            s0 = fmaf(v0.x, fa.x, s0); z0 = fmaf(v0.y, fa.y, z0);
            s0 = fmaf(v0.z, fb.x, s0); z0 = fmaf(v0.w, fb.y, z0);
            s1 = fmaf(v1.x, fa.x, s1); z1 = fmaf(v1.y, fa.y, z1);
            s1 = fmaf(v1.z, fb.x, s1); z1 = fmaf(v1.w, fb.y, z1);
            s2 = fmaf(v2.x, fa.x, s2); z2 = fmaf(v2.y, fa.y, z2);
            s2 = fmaf(v2.z, fb.x, s2); z2 = fmaf(v2.w, fb.y, z2);
            s3 = fmaf(v3.x, fa.x, s3); z3 = fmaf(v3.y, fa.y, z3);
            s3 = fmaf(v3.z, fb.x, s3); z3 = fmaf(v3.w, fb.y, z3);
        }
    }
    const float tw2v = __ldg(&tw2[ty * A + lane]);
    float u0 = tanh_approx(s0 + z0) * tw2v;
    float u1 = tanh_approx(s1 + z1) * tw2v;
    float u2 = tanh_approx(s2 + z2) * tw2v;
    float u3 = tanh_approx(s3 + z3) * tw2v;

    #pragma unroll
    for (int off = 16; off > 0; off >>= 1) {
        u0 += __shfl_xor_sync(0xffffffffu, u0, off);
        u1 += __shfl_xor_sync(0xffffffffu, u1, off);
        u2 += __shfl_xor_sync(0xffffffffu, u2, off);
        u3 += __shfl_xor_sync(0xffffffffu, u3, off);
    }

    // ---- softmax over T=4 + attended embedding (lane = d) ----
    const float m  = fmaxf(fmaxf(u0, u1), fmaxf(u2, u3));
    const float e0 = __expf(u0 - m), e1 = __expf(u1 - m);
    const float e2 = __expf(u2 - m), e3 = __expf(u3 - m);
    const float inv = 1.0f / (e0 + e1 + e2 + e3);
    sh_nat[wid][lane] = (e0 * acc[0] + e1 * acc[1] +
                         e2 * acc[2] + e3 * acc[3]) * inv;
    __syncwarp();

    // ---- projection: lane owns e in [4*lane, 4*lane+4); fp16 weights ----
    const __half* wb = g_twh + (size_t)ty * (D * E) + 4 * lane;
    float4 a4 = make_float4(0.f, 0.f, 0.f, 0.f);
    float4 b4 = make_float4(0.f, 0.f, 0.f, 0.f);
    const float4* np = (const float4*)sh_nat[wid];
    #pragma unroll
    for (int q = 0; q < D / 4; ++q) {
        const float4 n4 = np[q];           // broadcast LDS.128
        #pragma unroll
        for (int j = 0; j < 4; ++j) {
            const int d = 4 * q + j;
            const float nd = (j == 0) ? n4.x : (j == 1) ? n4.y
                           : (j == 2) ? n4.z : n4.w;
            const uint2 raw = __ldg((const uint2*)(wb + d * E)); // 4 halves
            const float2 f0 = __half22float2(*(const __half2*)&raw.x);
            const float2 f1 = __half22float2(*(const __half2*)&raw.y);
            if (j & 1) {
                b4.x = fmaf(nd, f0.x, b4.x); b4.y = fmaf(nd, f0.y, b4.y);
                b4.z = fmaf(nd, f1.x, b4.z); b4.w = fmaf(nd, f1.y, b4.w);
            } else {
                a4.x = fmaf(nd, f0.x, a4.x); a4.y = fmaf(nd, f0.y, a4.y);
                a4.z = fmaf(nd, f1.x, a4.z); a4.w = fmaf(nd, f1.y, a4.w);
            }
        }
    }

    const float4 val = make_float4(a4.x + b4.x + bv.x, a4.y + b4.y + bv.y,
                                   a4.z + b4.z + bv.z, a4.w + b4.w + bv.w);

    // ---- l2 norm: warp butterfly = exact sum over all 128 outputs ----
    float ss = val.x * val.x + val.y * val.y + val.z * val.z + val.w * val.w;
    #pragma unroll
    for (int off = 16; off > 0; off >>= 1)
        ss += __shfl_xor_sync(0xffffffffu, ss, off);
    const float r = rsqrtf(fmaxf(ss, 1e-12f));

    const float4 o = make_float4(val.x * r, val.y * r, val.z * r, val.w * r);
    ((float4*)(out + (size_t)b * E))[lane] = o;
}

extern "C" void kernel_launch(void* const* d_in, const int* in_sizes, int n_in,
                              void* d_out, int out_size) {
    const int*   targets   = (const int*)  d_in[0];
    const int*   types     = (const int*)  d_in[1];
    const int*   neighbors = (const int*)  d_in[2];
    const float* base_emb  = (const float*)d_in[3];
    const float* nte       = (const float*)d_in[4];
    const float* tw        = (const float*)d_in[5];
    const float* tw1       = (const float*)d_in[6];
    const float* tw2       = (const float*)d_in[7];
    float* out = (float*)d_out;

    const int B = in_sizes[0];

    k_convert<<<(T * D * E + 255) / 256, 256>>>(tw, tw1);

    const int grid = (B + NW - 1) / NW;

    // PDL launch: main kernel starts while k_convert drains; the in-kernel
    // cudaGridDependencySynchronize() provides the ordering on the fp16
    // tables. Falls back to a plain (stream-serialized) launch on error.
    cudaLaunchConfig_t cfg = {};
    cfg.gridDim  = dim3((unsigned)grid, 1, 1);
    cfg.blockDim = dim3(32 * NW, 1, 1);
    cfg.dynamicSmemBytes = 0;
    cfg.stream = 0;
    cudaLaunchAttribute attr;
    attr.id = cudaLaunchAttributeProgrammaticStreamSerialization;
    attr.val.programmaticStreamSerializationAllowed = 1;
    cfg.attrs = &attr;
    cfg.numAttrs = 1;

    const cudaError_t err = cudaLaunchKernelEx(
        &cfg, gatne_warp, targets, types, neighbors,
        base_emb, nte, tw2, out, B);
    if (err != cudaSuccess) {
        gatne_warp<<<grid, 32 * NW>>>(targets, types, neighbors,
                                      base_emb, nte, tw2, out, B);
    }
}

// round 15
// speedup vs baseline: 1.3243x; 1.3243x over previous
#include <cuda_runtime.h>
#include <cuda_fp16.h>
#include <cstddef>

// GATNE-T fused (R15): R13 body + IN-KERNEL fp16 weight conversion.
// Blocks 0..63 convert tw/tw1 to fp16 first and bump g_done; all blocks
// spin on g_done==64 only after their gather phase (wait hidden under
// gather latency). Self-resetting counters keep the kernel deterministic
// across graph replays. ONE kernel node total.
//
// Inputs (metadata order):
//  0 targets   int32  [B]
//  1 types     int32  [B]
//  2 neighbors int32  [B,T,S]
//  3 base_node_embeddings float [V,E]
//  4 node_type_embeddings float [V,T,D]
//  5 trans_weights    float [T,D,E]
//  6 trans_weights_s1 float [T,D,A]
//  7 trans_weights_s2 float [T,A,1]
// Output: float [B,E]

namespace {
constexpr int T = 4;
constexpr int S = 10;
constexpr int D = 32;
constexpr int E = 128;
constexpr int A = 32;
constexpr int NW = 8;              // warps per CTA
constexpr int CONV_BLOCKS = 64;    // 64 blocks x 256 thr = 16384 = T*D*E
}

__device__ __half  g_twh[T * D * E];            // [t][d][e]  (32KB)
__device__ __half2 g_tw1h2[T * (D / 2) * A];    // [t][dp][a]
__device__ volatile int g_done   = 0;           // converter blocks finished
__device__ int          g_passed = 0;           // blocks retired this launch

__device__ __forceinline__ float tanh_approx(float x) {
    float y;
    asm("tanh.approx.f32 %0, %1;" : "=f"(y) : "f"(x));
    return y;
}

__global__ __launch_bounds__(32 * NW, 5) void gatne_warp(
    const int*   __restrict__ targets,
    const int*   __restrict__ types,
    const int*   __restrict__ neighbors,  // [B,T,S]
    const float* __restrict__ base_emb,   // [V,E]
    const float* __restrict__ nte,        // [V,T,D]
    const float* __restrict__ tw,         // [T,D,E]
    const float* __restrict__ tw1,        // [T,D,A]
    const float* __restrict__ tw2,        // [T,A]
    float*       __restrict__ out,        // [B,E]
    int B)
{
    const int wid  = threadIdx.x >> 5;
    const int lane = threadIdx.x & 31;

    __shared__ float sh_agg[NW][T][D];
    __shared__ float sh_nat[NW][D];

    // ---- in-kernel weight conversion (blocks 0..63, before anything) ----
    if (blockIdx.x < CONV_BLOCKS) {
        const int i = blockIdx.x * 256 + threadIdx.x;      // 0..16383
        g_twh[i] = __float2half_rn(tw[i]);
        if (i < T * (D / 2) * A) {                         // 2048 elements
            const int t  = i / ((D / 2) * A);
            const int r  = i % ((D / 2) * A);
            const int dp = r / A;
            const int a  = r % A;
            const float* p = tw1 + (size_t)t * (D * A);
            g_tw1h2[i] = __floats2half2_rn(p[(2 * dp) * A + a],
                                           p[(2 * dp + 1) * A + a]);
        }
        __threadfence();
        __syncthreads();
        if (threadIdx.x == 0) atomicAdd((int*)&g_done, 1);
    }

    const int b = blockIdx.x * NW + wid;

    float acc[T];
    int ty = 0, tgt = 0;
    float4 bv = make_float4(0.f, 0.f, 0.f, 0.f);

    if (b < B) {
        ty  = types[b];      // broadcast LDG
        tgt = targets[b];    // broadcast LDG

        // PREFETCH random base_emb gather (overlaps neighbor gathers).
        bv = __ldg((const float4*)(base_emb + (size_t)tgt * E) + lane);

        // neighbor indices: 2 coalesced loads for 40 ints
        const int* nbp = neighbors + (size_t)b * (T * S);
        const int nbv0 = nbp[lane];
        const int nbv1 = (lane < T * S - 32) ? nbp[32 + lane] : 0;

        // gather + mean: two explicit 20-wide load batches (pinned MLP)
        float r0[2 * S];
        #pragma unroll
        for (int s = 0; s < S; ++s) {     // t = 0,1 : 20 loads in flight
            const int v0 = __shfl_sync(0xffffffffu, nbv0, s);
            const int v1 = __shfl_sync(0xffffffffu, nbv0, S + s);
            r0[s]     = __ldg(&nte[(size_t)v0 * (T * D) + 0 * D + lane]);
            r0[S + s] = __ldg(&nte[(size_t)v1 * (T * D) + 1 * D + lane]);
        }
        float a0 = 0.f, a1 = 0.f;
        #pragma unroll
        for (int s = 0; s < S; ++s) { a0 += r0[s]; a1 += r0[S + s]; }

        float r1[2 * S];
        #pragma unroll
        for (int s = 0; s < S; ++s) {     // t = 2,3 : next 20 loads
            const int flat2 = 2 * S + s;
            const int flat3 = 3 * S + s;
            const int v2 = __shfl_sync(0xffffffffu, nbv0, flat2);
            const int v3 = (flat3 < 32)
                ? __shfl_sync(0xffffffffu, nbv0, flat3)
                : __shfl_sync(0xffffffffu, nbv1, flat3 - 32);
            r1[s]     = __ldg(&nte[(size_t)v2 * (T * D) + 2 * D + lane]);
            r1[S + s] = __ldg(&nte[(size_t)v3 * (T * D) + 3 * D + lane]);
        }
        float a2 = 0.f, a3 = 0.f;
        #pragma unroll
        for (int s = 0; s < S; ++s) { a2 += r1[s]; a3 += r1[S + s]; }

        acc[0] = a0 * (1.0f / (float)S);
        acc[1] = a1 * (1.0f / (float)S);
        acc[2] = a2 * (1.0f / (float)S);
        acc[3] = a3 * (1.0f / (float)S);

        #pragma unroll
        for (int t = 0; t < T; ++t) sh_agg[wid][t][lane] = acc[t];
    }

    // ---- wait for converters (hidden under the gather latency above) ----
    if (threadIdx.x == 0) {
        while (g_done < CONV_BLOCKS) __nanosleep(64);
    }
    __syncthreads();
    __threadfence();   // acquire: order table reads after the spin

    if (b < B) {
        // ---- scores: fused 4-t loop, W1 loaded inline as half2 ----
        float s0 = 0.f, s1 = 0.f, s2 = 0.f, s3 = 0.f;
        float z0 = 0.f, z1 = 0.f, z2 = 0.f, z3 = 0.f;
        {
            const __half2* w1h = g_tw1h2 + (size_t)ty * ((D / 2) * A) + lane;
            const float4* ap0 = (const float4*)sh_agg[wid][0];
            const float4* ap1 = (const float4*)sh_agg[wid][1];
            const float4* ap2 = (const float4*)sh_agg[wid][2];
            const float4* ap3 = (const float4*)sh_agg[wid][3];
            #pragma unroll
            for (int q = 0; q < D / 4; ++q) {
                const float2 fa = __half22float2(w1h[(2 * q) * A]);
                const float2 fb = __half22float2(w1h[(2 * q + 1) * A]);
                const float4 v0 = ap0[q];
                const float4 v1 = ap1[q];
                const float4 v2 = ap2[q];
                const float4 v3 = ap3[q];
                s0 = fmaf(v0.x, fa.x, s0); z0 = fmaf(v0.y, fa.y, z0);
                s0 = fmaf(v0.z, fb.x, s0); z0 = fmaf(v0.w, fb.y, z0);
                s1 = fmaf(v1.x, fa.x, s1); z1 = fmaf(v1.y, fa.y, z1);
                s1 = fmaf(v1.z, fb.x, s1); z1 = fmaf(v1.w, fb.y, z1);
                s2 = fmaf(v2.x, fa.x, s2); z2 = fmaf(v2.y, fa.y, z2);
                s2 = fmaf(v2.z, fb.x, s2); z2 = fmaf(v2.w, fb.y, z2);
                s3 = fmaf(v3.x, fa.x, s3); z3 = fmaf(v3.y, fa.y, z3);
                s3 = fmaf(v3.z, fb.x, s3); z3 = fmaf(v3.w, fb.y, z3);
            }
        }
        const float tw2v = __ldg(&tw2[ty * A + lane]);
        float u0 = tanh_approx(s0 + z0) * tw2v;
        float u1 = tanh_approx(s1 + z1) * tw2v;
        float u2 = tanh_approx(s2 + z2) * tw2v;
        float u3 = tanh_approx(s3 + z3) * tw2v;

        #pragma unroll
        for (int off = 16; off > 0; off >>= 1) {
            u0 += __shfl_xor_sync(0xffffffffu, u0, off);
            u1 += __shfl_xor_sync(0xffffffffu, u1, off);
            u2 += __shfl_xor_sync(0xffffffffu, u2, off);
            u3 += __shfl_xor_sync(0xffffffffu, u3, off);
        }

        // ---- softmax over T=4 + attended embedding (lane = d) ----
        const float m  = fmaxf(fmaxf(u0, u1), fmaxf(u2, u3));
        const float e0 = __expf(u0 - m), e1 = __expf(u1 - m);
        const float e2 = __expf(u2 - m), e3 = __expf(u3 - m);
        const float inv = 1.0f / (e0 + e1 + e2 + e3);
        sh_nat[wid][lane] = (e0 * acc[0] + e1 * acc[1] +
                             e2 * acc[2] + e3 * acc[3]) * inv;
        __syncwarp();

        // ---- projection: lane owns e in [4*lane, 4*lane+4); fp16 weights --
        const __half* wb = g_twh + (size_t)ty * (D * E) + 4 * lane;
        float4 a4 = make_float4(0.f, 0.f, 0.f, 0.f);
        float4 b4 = make_float4(0.f, 0.f, 0.f, 0.f);
        const float4* np = (const float4*)sh_nat[wid];
        #pragma unroll
        for (int q = 0; q < D / 4; ++q) {
            const float4 n4 = np[q];       // broadcast LDS.128
            #pragma unroll
            for (int j = 0; j < 4; ++j) {
                const int d = 4 * q + j;
                const float nd = (j == 0) ? n4.x : (j == 1) ? n4.y
                               : (j == 2) ? n4.z : n4.w;
                const uint2 raw = __ldg((const uint2*)(wb + d * E));
                const float2 f0 = __half22float2(*(const __half2*)&raw.x);
                const float2 f1 = __half22float2(*(const __half2*)&raw.y);
                if (j & 1) {
                    b4.x = fmaf(nd, f0.x, b4.x); b4.y = fmaf(nd, f0.y, b4.y);
                    b4.z = fmaf(nd, f1.x, b4.z); b4.w = fmaf(nd, f1.y, b4.w);
                } else {
                    a4.x = fmaf(nd, f0.x, a4.x); a4.y = fmaf(nd, f0.y, a4.y);
                    a4.z = fmaf(nd, f1.x, a4.z); a4.w = fmaf(nd, f1.y, a4.w);
                }
            }
        }

        const float4 val = make_float4(a4.x + b4.x + bv.x, a4.y + b4.y + bv.y,
                                       a4.z + b4.z + bv.z, a4.w + b4.w + bv.w);

        // ---- l2 norm: warp butterfly = exact sum over all 128 outputs ----
        float ss = val.x * val.x + val.y * val.y
                 + val.z * val.z + val.w * val.w;
        #pragma unroll
        for (int off = 16; off > 0; off >>= 1)
            ss += __shfl_xor_sync(0xffffffffu, ss, off);
        const float r = rsqrtf(fmaxf(ss, 1e-12f));

        const float4 o = make_float4(val.x * r, val.y * r,
                                     val.z * r, val.w * r);
        ((float4*)(out + (size_t)b * E))[lane] = o;
    }

    // ---- retire: last block to exit resets the counters (deterministic
    //      across graph replays; runs after every block passed its spin) ----
    __syncthreads();
    if (threadIdx.x == 0) {
        __threadfence();
        const int p = atomicAdd(&g_passed, 1);
        if (p == (int)gridDim.x - 1) {
            g_passed = 0;
            g_done   = 0;
            __threadfence();
        }
    }
}

extern "C" void kernel_launch(void* const* d_in, const int* in_sizes, int n_in,
                              void* d_out, int out_size) {
    const int*   targets   = (const int*)  d_in[0];
    const int*   types     = (const int*)  d_in[1];
    const int*   neighbors = (const int*)  d_in[2];
    const float* base_emb  = (const float*)d_in[3];
    const float* nte       = (const float*)d_in[4];
    const float* tw        = (const float*)d_in[5];
    const float* tw1       = (const float*)d_in[6];
    const float* tw2       = (const float*)d_in[7];
    float* out = (float*)d_out;

    const int B = in_sizes[0];
    int grid = (B + NW - 1) / NW;
    if (grid < CONV_BLOCKS) grid = CONV_BLOCKS;   // ensure converters exist

    gatne_warp<<<grid, 32 * NW>>>(targets, types, neighbors,
                                  base_emb, nte, tw, tw1, tw2, out, B);
}

// round 16
// speedup vs baseline: 1.3266x; 1.0017x over previous
#include <cuda_runtime.h>
#include <cuda_fp16.h>
#include <cstddef>

// GATNE-T (R16): two-kernel split with fully-prefetched compute kernel.
// K1: neighbor gather + mean -> g_agg[B,T,D]; blocks 0..63 also convert
//     tw/tw1 to fp16 tables (kernel boundary orders tables before K2).
// K2: attention + projection + l2norm, ALL memory deps prefetched at top.
//
// Inputs (metadata order):
//  0 targets   int32  [B]
//  1 types     int32  [B]
//  2 neighbors int32  [B,T,S]
//  3 base_node_embeddings float [V,E]
//  4 node_type_embeddings float [V,T,D]
//  5 trans_weights    float [T,D,E]
//  6 trans_weights_s1 float [T,D,A]
//  7 trans_weights_s2 float [T,A,1]
// Output: float [B,E]

namespace {
constexpr int T = 4;
constexpr int S = 10;
constexpr int D = 32;
constexpr int E = 128;
constexpr int A = 32;
constexpr int NW = 8;              // warps per CTA
constexpr int MAXB = 8192;
constexpr int CONV_BLOCKS = 64;    // 64 x 256 = 16384 = T*D*E
}

__device__ float   g_agg[MAXB * T * D];         // aggregated neighbor means
__device__ __half  g_twh[T * D * E];            // fp16 trans_weights (32KB)
__device__ __half2 g_tw1h2[T * (D / 2) * A];    // packed fp16 W1

__device__ __forceinline__ float tanh_approx(float x) {
    float y;
    asm("tanh.approx.f32 %0, %1;" : "=f"(y) : "f"(x));
    return y;
}

// ---------------------------------------------------------------------------
// K1: gather (+ weight conversion in the first 64 blocks).
// ---------------------------------------------------------------------------
__global__ __launch_bounds__(32 * NW) void k1_gather(
    const int*   __restrict__ neighbors,  // [B,T,S]
    const float* __restrict__ nte,        // [V,T,D]
    const float* __restrict__ tw,         // [T,D,E]
    const float* __restrict__ tw1,        // [T,D,A]
    int B)
{
    // weight conversion: tiny, fully parallel, done by wave-1 blocks
    if (blockIdx.x < CONV_BLOCKS) {
        const int i = blockIdx.x * 256 + threadIdx.x;   // 0..16383
        g_twh[i] = __float2half_rn(tw[i]);
        if (i < T * (D / 2) * A) {
            const int t  = i / ((D / 2) * A);
            const int r  = i % ((D / 2) * A);
            const int dp = r / A;
            const int a  = r % A;
            const float* p = tw1 + (size_t)t * (D * A);
            g_tw1h2[i] = __floats2half2_rn(p[(2 * dp) * A + a],
                                           p[(2 * dp + 1) * A + a]);
        }
    }

    const int wid  = threadIdx.x >> 5;
    const int lane = threadIdx.x & 31;
    const int b = blockIdx.x * NW + wid;
    if (b >= B) return;

    // neighbor indices: 2 coalesced loads for 40 ints, broadcast via shfl
    const int* nbp = neighbors + (size_t)b * (T * S);
    const int nbv0 = nbp[lane];
    const int nbv1 = (lane < T * S - 32) ? nbp[32 + lane] : 0;

    // 40 independent coalesced 128B loads (two 20-wide batches)
    float a0 = 0.f, a1 = 0.f, a2 = 0.f, a3 = 0.f;
    {
        float r0[2 * S];
        #pragma unroll
        for (int s = 0; s < S; ++s) {
            const int v0 = __shfl_sync(0xffffffffu, nbv0, s);
            const int v1 = __shfl_sync(0xffffffffu, nbv0, S + s);
            r0[s]     = __ldg(&nte[(size_t)v0 * (T * D) + 0 * D + lane]);
            r0[S + s] = __ldg(&nte[(size_t)v1 * (T * D) + 1 * D + lane]);
        }
        #pragma unroll
        for (int s = 0; s < S; ++s) { a0 += r0[s]; a1 += r0[S + s]; }

        float r1[2 * S];
        #pragma unroll
        for (int s = 0; s < S; ++s) {
            const int flat2 = 2 * S + s;
            const int flat3 = 3 * S + s;
            const int v2 = __shfl_sync(0xffffffffu, nbv0, flat2);
            const int v3 = (flat3 < 32)
                ? __shfl_sync(0xffffffffu, nbv0, flat3)
                : __shfl_sync(0xffffffffu, nbv1, flat3 - 32);
            r1[s]     = __ldg(&nte[(size_t)v2 * (T * D) + 2 * D + lane]);
            r1[S + s] = __ldg(&nte[(size_t)v3 * (T * D) + 3 * D + lane]);
        }
        #pragma unroll
        for (int s = 0; s < S; ++s) { a2 += r1[s]; a3 += r1[S + s]; }
    }

    float* ap = g_agg + (size_t)b * (T * D) + lane;
    const float is = 1.0f / (float)S;
    ap[0 * D] = a0 * is;   // 4 coalesced 128B stores
    ap[1 * D] = a1 * is;
    ap[2 * D] = a2 * is;
    ap[3 * D] = a3 * is;
}

// ---------------------------------------------------------------------------
// K2: attention + projection + l2norm, everything prefetched at warp start.
// ---------------------------------------------------------------------------
__global__ __launch_bounds__(32 * NW, 5) void k2_compute(
    const int*   __restrict__ targets,
    const int*   __restrict__ types,
    const float* __restrict__ base_emb,   // [V,E]
    const float* __restrict__ tw2,        // [T,A]
    float*       __restrict__ out,        // [B,E]
    int B)
{
    const int wid  = threadIdx.x >> 5;
    const int lane = threadIdx.x & 31;

    __shared__ float sh_agg[NW][T][D];
    __shared__ float sh_nat[NW][D];

    const int b = blockIdx.x * NW + wid;
    if (b >= B) return;

    const int ty  = types[b];      // broadcast LDG
    const int tgt = targets[b];    // broadcast LDG

    // ---- PREFETCH EVERYTHING (independent loads, issued back-to-back) ----
    // 1) random base_emb gather (DRAM, ~600cyc) — the long pole
    const float4 bv = __ldg((const float4*)(base_emb + (size_t)tgt * E) + lane);
    // 2) agg rows (coalesced, L2-resident 4MB scratch)
    const float* agp = g_agg + (size_t)b * (T * D) + lane;
    const float acc0 = agp[0 * D];
    const float acc1 = agp[1 * D];
    const float acc2 = agp[2 * D];
    const float acc3 = agp[3 * D];
    // 3) attention weights (L1-resident table), packed half2
    __half2 w1p[D / 2];
    {
        const __half2* w1h = g_tw1h2 + (size_t)ty * ((D / 2) * A) + lane;
        #pragma unroll
        for (int dp = 0; dp < D / 2; ++dp) w1p[dp] = __ldg(&w1h[dp * A]);
    }
    const float tw2v = __ldg(&tw2[ty * A + lane]);

    sh_agg[wid][0][lane] = acc0;
    sh_agg[wid][1][lane] = acc1;
    sh_agg[wid][2][lane] = acc2;
    sh_agg[wid][3][lane] = acc3;
    __syncwarp();

    // ---- scores: fused 4-t loop (register W1, smem agg broadcasts) ----
    float s0 = 0.f, s1 = 0.f, s2 = 0.f, s3 = 0.f;
    float z0 = 0.f, z1 = 0.f, z2 = 0.f, z3 = 0.f;
    {
        const float4* ap0 = (const float4*)sh_agg[wid][0];
        const float4* ap1 = (const float4*)sh_agg[wid][1];
        const float4* ap2 = (const float4*)sh_agg[wid][2];
        const float4* ap3 = (const float4*)sh_agg[wid][3];
        #pragma unroll
        for (int q = 0; q < D / 4; ++q) {
            const float2 fa = __half22float2(w1p[2 * q]);
            const float2 fb = __half22float2(w1p[2 * q + 1]);
            const float4 v0 = ap0[q];
            const float4 v1 = ap1[q];
            const float4 v2 = ap2[q];
            const float4 v3 = ap3[q];
            s0 = fmaf(v0.x, fa.x, s0); z0 = fmaf(v0.y, fa.y, z0);
            s0 = fmaf(v0.z, fb.x, s0); z0 = fmaf(v0.w, fb.y, z0);
            s1 = fmaf(v1.x, fa.x, s1); z1 = fmaf(v1.y, fa.y, z1);
            s1 = fmaf(v1.z, fb.x, s1); z1 = fmaf(v1.w, fb.y, z1);
            s2 = fmaf(v2.x, fa.x, s2); z2 = fmaf(v2.y, fa.y, z2);
            s2 = fmaf(v2.z, fb.x, s2); z2 = fmaf(v2.w, fb.y, z2);
            s3 = fmaf(v3.x, fa.x, s3); z3 = fmaf(v3.y, fa.y, z3);
            s3 = fmaf(v3.z, fb.x, s3); z3 = fmaf(v3.w, fb.y, z3);
        }
    }
    float u0 = tanh_approx(s0 + z0) * tw2v;
    float u1 = tanh_approx(s1 + z1) * tw2v;
    float u2 = tanh_approx(s2 + z2) * tw2v;
    float u3 = tanh_approx(s3 + z3) * tw2v;

    #pragma unroll
    for (int off = 16; off > 0; off >>= 1) {
        u0 += __shfl_xor_sync(0xffffffffu, u0, off);
        u1 += __shfl_xor_sync(0xffffffffu, u1, off);
        u2 += __shfl_xor_sync(0xffffffffu, u2, off);
        u3 += __shfl_xor_sync(0xffffffffu, u3, off);
    }

    // ---- softmax over T=4 + attended embedding (lane = d) ----
    const float m  = fmaxf(fmaxf(u0, u1), fmaxf(u2, u3));
    const float e0 = __expf(u0 - m), e1 = __expf(u1 - m);
    const float e2 = __expf(u2 - m), e3 = __expf(u3 - m);
    const float inv = 1.0f / (e0 + e1 + e2 + e3);
    sh_nat[wid][lane] = (e0 * acc0 + e1 * acc1 +
                         e2 * acc2 + e3 * acc3) * inv;
    __syncwarp();

    // ---- projection: lane owns e in [4*lane, 4*lane+4); fp16 weights ----
    const __half* wb = g_twh + (size_t)ty * (D * E) + 4 * lane;
    float4 a4 = make_float4(0.f, 0.f, 0.f, 0.f);
    float4 b4 = make_float4(0.f, 0.f, 0.f, 0.f);
    const float4* np = (const float4*)sh_nat[wid];
    #pragma unroll
    for (int q = 0; q < D / 4; ++q) {
        const float4 n4 = np[q];           // broadcast LDS.128
        #pragma unroll
        for (int j = 0; j < 4; ++j) {
            const int d = 4 * q + j;
            const float nd = (j == 0) ? n4.x : (j == 1) ? n4.y
                           : (j == 2) ? n4.z : n4.w;
            const uint2 raw = __ldg((const uint2*)(wb + d * E)); // 4 halves
            const float2 f0 = __half22float2(*(const __half2*)&raw.x);
            const float2 f1 = __half22float2(*(const __half2*)&raw.y);
            if (j & 1) {
                b4.x = fmaf(nd, f0.x, b4.x); b4.y = fmaf(nd, f0.y, b4.y);
                b4.z = fmaf(nd, f1.x, b4.z); b4.w = fmaf(nd, f1.y, b4.w);
            } else {
                a4.x = fmaf(nd, f0.x, a4.x); a4.y = fmaf(nd, f0.y, a4.y);
                a4.z = fmaf(nd, f1.x, a4.z); a4.w = fmaf(nd, f1.y, a4.w);
            }
        }
    }

    const float4 val = make_float4(a4.x + b4.x + bv.x, a4.y + b4.y + bv.y,
                                   a4.z + b4.z + bv.z, a4.w + b4.w + bv.w);

    // ---- l2 norm: warp butterfly = exact sum over all 128 outputs ----
    float ss = val.x * val.x + val.y * val.y + val.z * val.z + val.w * val.w;
    #pragma unroll
    for (int off = 16; off > 0; off >>= 1)
        ss += __shfl_xor_sync(0xffffffffu, ss, off);
    const float r = rsqrtf(fmaxf(ss, 1e-12f));

    const float4 o = make_float4(val.x * r, val.y * r, val.z * r, val.w * r);
    ((float4*)(out + (size_t)b * E))[lane] = o;
}

extern "C" void kernel_launch(void* const* d_in, const int* in_sizes, int n_in,
                              void* d_out, int out_size) {
    const int*   targets   = (const int*)  d_in[0];
    const int*   types     = (const int*)  d_in[1];
    const int*   neighbors = (const int*)  d_in[2];
    const float* base_emb  = (const float*)d_in[3];
    const float* nte       = (const float*)d_in[4];
    const float* tw        = (const float*)d_in[5];
    const float* tw1       = (const float*)d_in[6];
    const float* tw2       = (const float*)d_in[7];
    float* out = (float*)d_out;

    const int B = in_sizes[0];
    int grid = (B + NW - 1) / NW;
    if (grid < CONV_BLOCKS) grid = CONV_BLOCKS;

    k1_gather <<<grid, 32 * NW>>>(neighbors, nte, tw, tw1, B);
    k2_compute<<<(B + NW - 1) / NW, 32 * NW>>>(targets, types, base_emb,
                                               tw2, out, B);
}

// round 17
// speedup vs baseline: 1.3402x; 1.0103x over previous
#include <cuda_runtime.h>
#include <cstddef>

// GATNE-T fused (R17): R13 skeleton, fp32 weights, packed f32x2 FMA
// (fma.rn.f32x2) in the score and projection loops. Single kernel launch,
// no weight-conversion pass.
//
// Inputs (metadata order):
//  0 targets   int32  [B]
//  1 types     int32  [B]
//  2 neighbors int32  [B,T,S]
//  3 base_node_embeddings float [V,E]
//  4 node_type_embeddings float [V,T,D]
//  5 trans_weights    float [T,D,E]
//  6 trans_weights_s1 float [T,D,A]
//  7 trans_weights_s2 float [T,A,1]
// Output: float [B,E]

namespace {
constexpr int T = 4;
constexpr int S = 10;
constexpr int D = 32;
constexpr int E = 128;
constexpr int A = 32;
constexpr int NW = 8;          // warps per CTA
}

__device__ __forceinline__ float tanh_approx(float x) {
    float y;
    asm("tanh.approx.f32 %0, %1;" : "=f"(y) : "f"(x));
    return y;
}

// ---- packed f32x2 helpers (Blackwell; ptxas won't auto-fuse these) ----
__device__ __forceinline__ unsigned long long pk2(float lo, float hi) {
    unsigned long long r;
    asm("mov.b64 %0, {%1, %2};" : "=l"(r) : "f"(lo), "f"(hi));
    return r;
}
__device__ __forceinline__ unsigned long long fma2(
    unsigned long long a, unsigned long long b, unsigned long long c) {
    unsigned long long d;
    asm("fma.rn.f32x2 %0, %1, %2, %3;" : "=l"(d) : "l"(a), "l"(b), "l"(c));
    return d;
}
__device__ __forceinline__ float2 unpk2(unsigned long long v) {
    float lo, hi;
    asm("mov.b64 {%0, %1}, %2;" : "=f"(lo), "=f"(hi) : "l"(v));
    return make_float2(lo, hi);
}

__global__ __launch_bounds__(32 * NW, 5) void gatne_warp(
    const int*   __restrict__ targets,
    const int*   __restrict__ types,
    const int*   __restrict__ neighbors,  // [B,T,S]
    const float* __restrict__ base_emb,   // [V,E]
    const float* __restrict__ nte,        // [V,T,D]
    const float* __restrict__ tw,         // [T,D,E]
    const float* __restrict__ tw1,        // [T,D,A]
    const float* __restrict__ tw2,        // [T,A]
    float*       __restrict__ out,        // [B,E]
    int B)
{
    const int wid  = threadIdx.x >> 5;
    const int lane = threadIdx.x & 31;

    __shared__ float sh_agg[NW][T][D];
    __shared__ float sh_nat[NW][D];

    const int b = blockIdx.x * NW + wid;
    if (b >= B) return;

    const int ty  = types[b];      // broadcast LDG
    const int tgt = targets[b];    // broadcast LDG

    // PREFETCH the random base_emb gather (overlaps neighbor gathers).
    const float4 bv = __ldg((const float4*)(base_emb + (size_t)tgt * E) + lane);

    // neighbor indices: 2 coalesced loads for 40 ints
    const int* nbp = neighbors + (size_t)b * (T * S);
    const int nbv0 = nbp[lane];
    const int nbv1 = (lane < T * S - 32) ? nbp[32 + lane] : 0;

    // ---- gather + mean: two explicit 20-wide load batches (pinned MLP) ----
    float acc[T];
    {
        float r0[2 * S];
        #pragma unroll
        for (int s = 0; s < S; ++s) {     // t = 0,1 : 20 loads in flight
            const int v0 = __shfl_sync(0xffffffffu, nbv0, s);
            const int v1 = __shfl_sync(0xffffffffu, nbv0, S + s);
            r0[s]     = __ldg(&nte[(size_t)v0 * (T * D) + 0 * D + lane]);
            r0[S + s] = __ldg(&nte[(size_t)v1 * (T * D) + 1 * D + lane]);
        }
        float a0 = 0.f, a1 = 0.f;
        #pragma unroll
        for (int s = 0; s < S; ++s) { a0 += r0[s]; a1 += r0[S + s]; }

        float r1[2 * S];
        #pragma unroll
        for (int s = 0; s < S; ++s) {     // t = 2,3 : next 20 loads
            const int flat2 = 2 * S + s;
            const int flat3 = 3 * S + s;
            const int v2 = __shfl_sync(0xffffffffu, nbv0, flat2);
            const int v3 = (flat3 < 32)
                ? __shfl_sync(0xffffffffu, nbv0, flat3)
                : __shfl_sync(0xffffffffu, nbv1, flat3 - 32);
            r1[s]     = __ldg(&nte[(size_t)v2 * (T * D) + 2 * D + lane]);
            r1[S + s] = __ldg(&nte[(size_t)v3 * (T * D) + 3 * D + lane]);
        }
        float a2 = 0.f, a3 = 0.f;
        #pragma unroll
        for (int s = 0; s < S; ++s) { a2 += r1[s]; a3 += r1[S + s]; }

        acc[0] = a0 * (1.0f / (float)S);
        acc[1] = a1 * (1.0f / (float)S);
        acc[2] = a2 * (1.0f / (float)S);
        acc[3] = a3 * (1.0f / (float)S);
    }

    #pragma unroll
    for (int t = 0; t < T; ++t) sh_agg[wid][t][lane] = acc[t];
    __syncwarp();

    // ---- scores: fused 4-t loop, packed f32x2 FMAs over d-pairs ----
    // acc pair for t accumulates (d-even, d-odd) partial sums elementwise.
    unsigned long long p0 = 0, p1 = 0, p2 = 0, p3 = 0;  // (0.0f,0.0f) packs
    {
        const float* w1 = tw1 + (size_t)ty * (D * A) + lane;   // lane = a
        const float4* ap0 = (const float4*)sh_agg[wid][0];
        const float4* ap1 = (const float4*)sh_agg[wid][1];
        const float4* ap2 = (const float4*)sh_agg[wid][2];
        const float4* ap3 = (const float4*)sh_agg[wid][3];
        #pragma unroll
        for (int q = 0; q < D / 4; ++q) {
            // 4 coalesced W1 row loads (L1-resident, 1 wf each)
            const float wd0 = __ldg(w1 + (4 * q + 0) * A);
            const float wd1 = __ldg(w1 + (4 * q + 1) * A);
            const float wd2 = __ldg(w1 + (4 * q + 2) * A);
            const float wd3 = __ldg(w1 + (4 * q + 3) * A);
            const unsigned long long wp0 = pk2(wd0, wd1);
            const unsigned long long wp1 = pk2(wd2, wd3);

            const float4 v0 = ap0[q];          // LDS.128 broadcasts
            const float4 v1 = ap1[q];
            const float4 v2 = ap2[q];
            const float4 v3 = ap3[q];

            p0 = fma2(pk2(v0.x, v0.y), wp0, p0);
            p0 = fma2(pk2(v0.z, v0.w), wp1, p0);
            p1 = fma2(pk2(v1.x, v1.y), wp0, p1);
            p1 = fma2(pk2(v1.z, v1.w), wp1, p1);
            p2 = fma2(pk2(v2.x, v2.y), wp0, p2);
            p2 = fma2(pk2(v2.z, v2.w), wp1, p2);
            p3 = fma2(pk2(v3.x, v3.y), wp0, p3);
            p3 = fma2(pk2(v3.z, v3.w), wp1, p3);
        }
    }
    const float tw2v = __ldg(&tw2[ty * A + lane]);
    const float2 f0 = unpk2(p0);
    const float2 f1 = unpk2(p1);
    const float2 f2 = unpk2(p2);
    const float2 f3 = unpk2(p3);
    float u0 = tanh_approx(f0.x + f0.y) * tw2v;
    float u1 = tanh_approx(f1.x + f1.y) * tw2v;
    float u2 = tanh_approx(f2.x + f2.y) * tw2v;
    float u3 = tanh_approx(f3.x + f3.y) * tw2v;

    #pragma unroll
    for (int off = 16; off > 0; off >>= 1) {
        u0 += __shfl_xor_sync(0xffffffffu, u0, off);
        u1 += __shfl_xor_sync(0xffffffffu, u1, off);
        u2 += __shfl_xor_sync(0xffffffffu, u2, off);
        u3 += __shfl_xor_sync(0xffffffffu, u3, off);
    }

    // ---- softmax over T=4 + attended embedding (lane = d) ----
    const float m  = fmaxf(fmaxf(u0, u1), fmaxf(u2, u3));
    const float e0 = __expf(u0 - m), e1 = __expf(u1 - m);
    const float e2 = __expf(u2 - m), e3 = __expf(u3 - m);
    const float inv = 1.0f / (e0 + e1 + e2 + e3);
    sh_nat[wid][lane] = (e0 * acc[0] + e1 * acc[1] +
                         e2 * acc[2] + e3 * acc[3]) * inv;
    __syncwarp();

    // ---- projection: lane owns e in [4*lane, 4*lane+4); fp32 weights,
    //      2 packed FFMA2 per d (accA = e-pair 01, accB = e-pair 23) ----
    const float* wbase = tw + (size_t)ty * (D * E) + 4 * lane;
    unsigned long long accA = 0, accB = 0;
    const float4* np = (const float4*)sh_nat[wid];
    #pragma unroll
    for (int q = 0; q < D / 4; ++q) {
        const float4 n4 = np[q];           // broadcast LDS.128
        #pragma unroll
        for (int j = 0; j < 4; ++j) {
            const int d = 4 * q + j;
            const float nd = (j == 0) ? n4.x : (j == 1) ? n4.y
                           : (j == 2) ? n4.z : n4.w;
            const float4 w4 = __ldg((const float4*)(wbase + d * E));
            const unsigned long long nd2 = pk2(nd, nd);
            accA = fma2(nd2, pk2(w4.x, w4.y), accA);
            accB = fma2(nd2, pk2(w4.z, w4.w), accB);
        }
    }
    const float2 pa = unpk2(accA);
    const float2 pb = unpk2(accB);

    const float4 val = make_float4(pa.x + bv.x, pa.y + bv.y,
                                   pb.x + bv.z, pb.y + bv.w);

    // ---- l2 norm: warp butterfly = exact sum over all 128 outputs ----
    float ss = val.x * val.x + val.y * val.y + val.z * val.z + val.w * val.w;
    #pragma unroll
    for (int off = 16; off > 0; off >>= 1)
        ss += __shfl_xor_sync(0xffffffffu, ss, off);
    const float r = rsqrtf(fmaxf(ss, 1e-12f));

    const float4 o = make_float4(val.x * r, val.y * r, val.z * r, val.w * r);
    ((float4*)(out + (size_t)b * E))[lane] = o;
}

extern "C" void kernel_launch(void* const* d_in, const int* in_sizes, int n_in,
                              void* d_out, int out_size) {
    const int*   targets   = (const int*)  d_in[0];
    const int*   types     = (const int*)  d_in[1];
    const int*   neighbors = (const int*)  d_in[2];
    const float* base_emb  = (const float*)d_in[3];
    const float* nte       = (const float*)d_in[4];
    const float* tw        = (const float*)d_in[5];
    const float* tw1       = (const float*)d_in[6];
    const float* tw2       = (const float*)d_in[7];
    float* out = (float*)d_out;

    const int B = in_sizes[0];
    const int grid = (B + NW - 1) / NW;
    gatne_warp<<<grid, 32 * NW>>>(targets, types, neighbors,
                                  base_emb, nte, tw, tw1, tw2, out, B);
}